// round 12
// baseline (speedup 1.0000x reference)
#include <cuda_runtime.h>
#include <cuda_bf16.h>
#include <cstdint>
#include <cstddef>

// Problem constants
#define NB    4096
#define L2DIM 49
#define CDIM  128
#define BAD   324
#define MPAD  336     // ba padded to 21 x 16 (GEMM1 M)
#define KPAD  64      // i padded (GEMM1 K)
#define IPAD  64      // i padded (GEMM2 M)
#define KBA   384     // ba padded (WfT row length, 48 x 16B chunks)
#define NTHR  512
#define CHUNK 112

typedef uint32_t u32;

// Bank swizzle: permute 16B chunks within a row; rows r and r+8 map differently
// in the low 3 bits so ldmatrix x4 half-tiles never collide.
__device__ __forceinline__ int swz(int row, int chunk) {
    return chunk ^ ((row + (row >> 3)) & 7);
}

// ---------------- device globals: pre-split, pre-swizzled weights ----------------
__device__ __nv_bfloat16 g_WtoH[MPAD * 64];    // [ba][i] rows 128B
__device__ __nv_bfloat16 g_WtoL[MPAD * 64];
__device__ __nv_bfloat16 g_WfTH[IPAD * KBA];   // [i][ba] rows 768B
__device__ __nv_bfloat16 g_WfTL[IPAD * KBA];

__global__ void prep_kernel(const float* __restrict__ Wto,
                            const float* __restrict__ Wf) {
    int idx = blockIdx.x * blockDim.x + threadIdx.x;
    if (idx < MPAD * 64) {
        int row = idx >> 6, col = idx & 63;
        float w = (row < BAD && col < L2DIM) ? Wto[row * L2DIM + col] : 0.0f;
        __nv_bfloat16 h = __float2bfloat16(w);
        __nv_bfloat16 l = __float2bfloat16(w - __bfloat162float(h));
        int pos = row * 64 + swz(row, col >> 3) * 8 + (col & 7);
        g_WtoH[pos] = h;
        g_WtoL[pos] = l;
    }
    int idx2 = idx - MPAD * 64;
    if (idx2 >= 0 && idx2 < IPAD * KBA) {
        int row = idx2 / KBA, col = idx2 - row * KBA;  // row = i, col = ba
        float w = (row < L2DIM && col < BAD) ? Wf[col * L2DIM + row] : 0.0f;
        __nv_bfloat16 h = __float2bfloat16(w);
        __nv_bfloat16 l = __float2bfloat16(w - __bfloat162float(h));
        int pos = row * KBA + swz(row, col >> 3) * 8 + (col & 7);
        g_WfTH[pos] = h;
        g_WfTL[pos] = l;
    }
}

// ---------------- mma / ldmatrix wrappers ----------------
__device__ __forceinline__ void mma16816(float* d, uint4 a, u32 b0, u32 b1) {
    asm volatile(
        "mma.sync.aligned.m16n8k16.row.col.f32.bf16.bf16.f32 "
        "{%0,%1,%2,%3}, {%4,%5,%6,%7}, {%8,%9}, {%0,%1,%2,%3};"
        : "+f"(d[0]), "+f"(d[1]), "+f"(d[2]), "+f"(d[3])
        : "r"(a.x), "r"(a.y), "r"(a.z), "r"(a.w), "r"(b0), "r"(b1));
}
__device__ __forceinline__ uint4 ldsm4(u32 addr) {
    uint4 r;
    asm volatile("ldmatrix.sync.aligned.m8n8.x4.shared.b16 {%0,%1,%2,%3}, [%4];"
                 : "=r"(r.x), "=r"(r.y), "=r"(r.z), "=r"(r.w) : "r"(addr));
    return r;
}
__device__ __forceinline__ uint4 ldsm4t(u32 addr) {
    uint4 r;
    asm volatile("ldmatrix.sync.aligned.m8n8.x4.trans.shared.b16 {%0,%1,%2,%3}, [%4];"
                 : "=r"(r.x), "=r"(r.y), "=r"(r.z), "=r"(r.w) : "r"(addr));
    return r;
}
__device__ __forceinline__ u32 pkbf(float a, float b) {
    __nv_bfloat162 t = __floats2bfloat162_rn(a, b);
    u32 r;
    memcpy(&r, &t, 4);
    return r;
}

// ---------------- SMEM layout (byte offsets), total 217088 ----------------
#define XS_H   0        // [64][128] bf16 rows 256B  (16384)
#define XS_L   16384
#define WTS_H  32768    // [112][64] bf16 rows 128B  (14336)
#define WTS_L  47104
#define G2_H   61440    // [112][128] bf16 rows 256B (28672)
#define G2_L   90112
#define WFT_H  118784   // [64][384] bf16 rows 768B  (49152)
#define WFT_L  167936
#define SMEM_BYTES 217088

__global__ void __launch_bounds__(NTHR, 1)
fused_kernel(const float* __restrict__ X, float* __restrict__ Out) {
    extern __shared__ __align__(16) char smem[];
    u32 smem_u32;
    asm("{ .reg .u64 t; cvta.to.shared.u64 t, %1; cvt.u32.u64 %0, t; }"
        : "=r"(smem_u32) : "l"(smem));

    const int n    = blockIdx.x;
    const int tid  = threadIdx.x;
    const int wrp  = tid >> 5;
    const int lane = tid & 31;
    const int gg   = lane >> 2;   // mma fragment row group
    const int tc   = lane & 3;    // mma fragment col/thread-in-group

    // ---------- stage X[n] split (hi/lo) + zero pad, and WfT copy ----------
    {
        const float2* X2 = reinterpret_cast<const float2*>(X + (size_t)n * L2DIM * CDIM);
        u32* xh = reinterpret_cast<u32*>(smem + XS_H);
        u32* xl = reinterpret_cast<u32*>(smem + XS_L);
        for (int p = tid; p < L2DIM * 64; p += NTHR) {
            int i = p >> 6, cp = p & 63;
            float2 v = X2[p];
            __nv_bfloat16 h0 = __float2bfloat16(v.x);
            __nv_bfloat16 h1 = __float2bfloat16(v.y);
            float r0 = v.x - __bfloat162float(h0);
            float r1 = v.y - __bfloat162float(h1);
            int uidx = i * 64 + swz(i, cp >> 2) * 4 + (cp & 3);
            xh[uidx] = pkbf(__bfloat162float(h0), __bfloat162float(h1));
            xl[uidx] = pkbf(r0, r1);
        }
        for (int p = tid; p < (KPAD - L2DIM) * 64; p += NTHR) {
            int i = L2DIM + p / 64, c = p % 64;
            xh[i * 64 + c] = 0u;
            xl[i * 64 + c] = 0u;
        }
        uint4* sh = reinterpret_cast<uint4*>(smem + WFT_H);
        uint4* sl = reinterpret_cast<uint4*>(smem + WFT_L);
        const uint4* gh = reinterpret_cast<const uint4*>(g_WfTH);
        const uint4* gl = reinterpret_cast<const uint4*>(g_WfTL);
        for (int p = tid; p < IPAD * KBA * 2 / 16; p += NTHR) {
            sh[p] = gh[p];
            sl[p] = gl[p];
        }
    }

    // GEMM2 output accumulators (live across chunks)
    float d2[4][4];
#pragma unroll
    for (int a = 0; a < 4; a++)
#pragma unroll
        for (int b = 0; b < 4; b++) d2[a][b] = 0.0f;

    const int mtw = wrp >> 2;   // GEMM2: i-tile (rows mtw*16..+15)
    const int ntw = wrp & 3;    // GEMM2: c-group (cols ntw*32..+31)

    for (int ch = 0; ch < 3; ch++) {
        const int cbase = ch * CHUNK;
        __syncthreads();   // prev GEMM2 reads done before restage/epilogue
        // stage Wto chunk (raw copy; swizzle already applied with global rows)
        {
            uint4* sh = reinterpret_cast<uint4*>(smem + WTS_H);
            uint4* sl = reinterpret_cast<uint4*>(smem + WTS_L);
            const uint4* gh = reinterpret_cast<const uint4*>(g_WtoH) + cbase * 8;
            const uint4* gl = reinterpret_cast<const uint4*>(g_WtoL) + cbase * 8;
            for (int p = tid; p < CHUNK * 8; p += NTHR) {
                sh[p] = gh[p];
                sl[p] = gl[p];
            }
        }
        __syncthreads();

        // ---------------- GEMM1: D1[ba_local 112][c 128] ----------------
        if (wrp < 14) {
            const int mt = wrp >> 1;   // 0..6: rows mt*16..+15
            const int nt = wrp & 1;    // cols nt*64..+63
            float d1[8][4];
#pragma unroll
            for (int a = 0; a < 8; a++)
#pragma unroll
                for (int b = 0; b < 4; b++) d1[a][b] = 0.0f;

#pragma unroll
            for (int pass = 0; pass < 3; pass++) {
                const u32 abase = smem_u32 + (pass == 2 ? WTS_L : WTS_H);
                const u32 bbase = smem_u32 + (pass == 1 ? XS_L : XS_H);
#pragma unroll
                for (int ks = 0; ks < 4; ks++) {
                    int arow = mt * 16 + ((lane >> 3) & 1) * 8 + (lane & 7);
                    int achk = ks * 2 + (lane >> 4);
                    uint4 A = ldsm4(abase + arow * 128 + swz(cbase + arow, achk) * 16);
                    int krow = ks * 16 + ((lane >> 3) & 1) * 8 + (lane & 7);
#pragma unroll
                    for (int j = 0; j < 4; j++) {
                        int nchk = nt * 8 + j * 2 + (lane >> 4);
                        uint4 B = ldsm4t(bbase + krow * 256 + swz(krow, nchk) * 16);
                        mma16816(d1[2 * j],     A, B.x, B.y);
                        mma16816(d1[2 * j + 1], A, B.z, B.w);
                    }
                }
            }
            // epilogue: square, split hi/lo, store G2 (swizzled)
            u32* g2h = reinterpret_cast<u32*>(smem + G2_H);
            u32* g2l = reinterpret_cast<u32*>(smem + G2_L);
#pragma unroll
            for (int nn = 0; nn < 8; nn++) {
                int chk = nt * 8 + nn;
#pragma unroll
                for (int hr = 0; hr < 2; hr++) {
                    int row = mt * 16 + gg + hr * 8;
                    float s0 = d1[nn][hr * 2 + 0]; s0 *= s0;
                    float s1 = d1[nn][hr * 2 + 1]; s1 *= s1;
                    __nv_bfloat16 h0 = __float2bfloat16(s0);
                    __nv_bfloat16 h1 = __float2bfloat16(s1);
                    float r0 = s0 - __bfloat162float(h0);
                    float r1 = s1 - __bfloat162float(h1);
                    int uidx = row * 64 + swz(row, chk) * 4 + tc;
                    g2h[uidx] = pkbf(__bfloat162float(h0), __bfloat162float(h1));
                    g2l[uidx] = pkbf(r0, r1);
                }
            }
        }
        __syncthreads();

        // ---------------- GEMM2 partial: accumulate over this chunk's 112 ba ----------------
#pragma unroll
        for (int pass = 0; pass < 3; pass++) {
            const u32 abase = smem_u32 + (pass == 2 ? WFT_L : WFT_H);
            const u32 bbase = smem_u32 + (pass == 1 ? G2_L : G2_H);
#pragma unroll
            for (int ks = 0; ks < 7; ks++) {
                int arow = mtw * 16 + ((lane >> 3) & 1) * 8 + (lane & 7);
                int achk = cbase / 8 + ks * 2 + (lane >> 4);
                uint4 A = ldsm4(abase + arow * 768 + swz(arow, achk) * 16);
                int krow = ks * 16 + ((lane >> 3) & 1) * 8 + (lane & 7);
#pragma unroll
                for (int j = 0; j < 2; j++) {
                    int nchk = ntw * 4 + j * 2 + (lane >> 4);
                    uint4 B = ldsm4t(bbase + krow * 256 + swz(krow, nchk) * 16);
                    mma16816(d2[2 * j],     A, B.x, B.y);
                    mma16816(d2[2 * j + 1], A, B.z, B.w);
                }
            }
        }
    }

    // ---------------- writeout: D2[i][c] fp32 ----------------
    float2* O2 = reinterpret_cast<float2*>(Out + (size_t)n * L2DIM * CDIM);
#pragma unroll
    for (int nf = 0; nf < 4; nf++) {
        int c  = ntw * 32 + nf * 8 + tc * 2;
        int i0 = mtw * 16 + gg;
        if (i0 < L2DIM) O2[i0 * 64 + (c >> 1)] = make_float2(d2[nf][0], d2[nf][1]);
        int i1 = i0 + 8;
        if (i1 < L2DIM) O2[i1 * 64 + (c >> 1)] = make_float2(d2[nf][2], d2[nf][3]);
    }
}

// ---------------- launcher ----------------
extern "C" void kernel_launch(void* const* d_in, const int* in_sizes, int n_in,
                              void* d_out, int out_size) {
    const float* X   = (const float*)d_in[0];  // inputs  (N, 49, 128)
    const float* Wto = (const float*)d_in[1];  // W_to    (18, 18, 49)
    const float* Wf  = (const float*)d_in[2];  // W_from  (18, 18, 49)
    float* Out = (float*)d_out;                // (N, 49, 128)

    static bool attr_set = false;
    if (!attr_set) {
        cudaFuncSetAttribute(fused_kernel,
                             cudaFuncAttributeMaxDynamicSharedMemorySize,
                             SMEM_BYTES);
        attr_set = true;
    }

    int prep_total = MPAD * 64 + IPAD * KBA;   // 46080
    prep_kernel<<<(prep_total + 255) / 256, 256>>>(Wto, Wf);

    fused_kernel<<<NB, NTHR, SMEM_BYTES>>>(X, Out);
}

// round 13
// speedup vs baseline: 1.0021x; 1.0021x over previous
#include <cuda_runtime.h>
#include <cuda_bf16.h>
#include <cstdint>
#include <cstddef>

// Problem constants
#define NB    4096
#define L2DIM 49
#define CDIM  128
#define BAD   324
#define MPAD  336     // ba padded to 21 x 16 (GEMM1 M)
#define KPAD  64      // i padded (GEMM1 K)
#define IPAD  64      // i padded (GEMM2 M)
#define KBA   384     // ba padded (WfT row length, 48 x 16B chunks)
#define NTHR  512
#define CHUNK 112

typedef uint32_t u32;

// Bank swizzle: permute 16B chunks within a row; rows r and r+8 map differently
// in the low 3 bits so ldmatrix x4 half-tiles never collide.
__device__ __forceinline__ int swz(int row, int chunk) {
    return chunk ^ ((row + (row >> 3)) & 7);
}

// ---------------- device globals: pre-split, pre-swizzled weights ----------------
__device__ __nv_bfloat16 g_WtoH[MPAD * 64];    // [ba][i] rows 128B
__device__ __nv_bfloat16 g_WtoL[MPAD * 64];
__device__ __nv_bfloat16 g_WfTH[IPAD * KBA];   // [i][ba] rows 768B
__device__ __nv_bfloat16 g_WfTL[IPAD * KBA];

__global__ void prep_kernel(const float* __restrict__ Wto,
                            const float* __restrict__ Wf) {
    int idx = blockIdx.x * blockDim.x + threadIdx.x;
    if (idx < MPAD * 64) {
        int row = idx >> 6, col = idx & 63;
        float w = (row < BAD && col < L2DIM) ? Wto[row * L2DIM + col] : 0.0f;
        __nv_bfloat16 h = __float2bfloat16(w);
        __nv_bfloat16 l = __float2bfloat16(w - __bfloat162float(h));
        int pos = row * 64 + swz(row, col >> 3) * 8 + (col & 7);
        g_WtoH[pos] = h;
        g_WtoL[pos] = l;
    }
    int idx2 = idx - MPAD * 64;
    if (idx2 >= 0 && idx2 < IPAD * KBA) {
        int row = idx2 / KBA, col = idx2 - row * KBA;  // row = i, col = ba
        float w = (row < L2DIM && col < BAD) ? Wf[col * L2DIM + row] : 0.0f;
        __nv_bfloat16 h = __float2bfloat16(w);
        __nv_bfloat16 l = __float2bfloat16(w - __bfloat162float(h));
        int pos = row * KBA + swz(row, col >> 3) * 8 + (col & 7);
        g_WfTH[pos] = h;
        g_WfTL[pos] = l;
    }
}

// ---------------- mma / ldmatrix wrappers ----------------
__device__ __forceinline__ void mma16816(float* d, uint4 a, u32 b0, u32 b1) {
    asm volatile(
        "mma.sync.aligned.m16n8k16.row.col.f32.bf16.bf16.f32 "
        "{%0,%1,%2,%3}, {%4,%5,%6,%7}, {%8,%9}, {%0,%1,%2,%3};"
        : "+f"(d[0]), "+f"(d[1]), "+f"(d[2]), "+f"(d[3])
        : "r"(a.x), "r"(a.y), "r"(a.z), "r"(a.w), "r"(b0), "r"(b1));
}
__device__ __forceinline__ uint4 ldsm4(u32 addr) {
    uint4 r;
    asm volatile("ldmatrix.sync.aligned.m8n8.x4.shared.b16 {%0,%1,%2,%3}, [%4];"
                 : "=r"(r.x), "=r"(r.y), "=r"(r.z), "=r"(r.w) : "r"(addr));
    return r;
}
__device__ __forceinline__ uint4 ldsm4t(u32 addr) {
    uint4 r;
    asm volatile("ldmatrix.sync.aligned.m8n8.x4.trans.shared.b16 {%0,%1,%2,%3}, [%4];"
                 : "=r"(r.x), "=r"(r.y), "=r"(r.z), "=r"(r.w) : "r"(addr));
    return r;
}
__device__ __forceinline__ u32 pkbf(float a, float b) {
    __nv_bfloat162 t = __floats2bfloat162_rn(a, b);
    u32 r;
    memcpy(&r, &t, 4);
    return r;
}

// ---------------- SMEM layout (byte offsets), total 217088 ----------------
#define XS_H   0        // [64][128] bf16 rows 256B  (16384)
#define XS_L   16384
#define WTS_H  32768    // [112][64] bf16 rows 128B  (14336)
#define WTS_L  47104
#define G2_H   61440    // [112][128] bf16 rows 256B (28672)
#define G2_L   90112
#define WFT_H  118784   // [64][384] bf16 rows 768B  (49152)
#define WFT_L  167936
#define SMEM_BYTES 217088

__global__ void __launch_bounds__(NTHR, 1)
fused_kernel(const float* __restrict__ X, float* __restrict__ Out) {
    extern __shared__ __align__(16) char smem[];
    u32 smem_u32;
    asm("{ .reg .u64 t; cvta.to.shared.u64 t, %1; cvt.u32.u64 %0, t; }"
        : "=r"(smem_u32) : "l"(smem));

    const int n    = blockIdx.x;
    const int tid  = threadIdx.x;
    const int wrp  = tid >> 5;
    const int lane = tid & 31;
    const int gg   = lane >> 2;   // mma fragment row group
    const int tc   = lane & 3;    // mma fragment col/thread-in-group

    // ---------- stage X[n] split (hi/lo) + zero pad, and WfT copy ----------
    {
        const float2* X2 = reinterpret_cast<const float2*>(X + (size_t)n * L2DIM * CDIM);
        u32* xh = reinterpret_cast<u32*>(smem + XS_H);
        u32* xl = reinterpret_cast<u32*>(smem + XS_L);
        for (int p = tid; p < L2DIM * 64; p += NTHR) {
            int i = p >> 6, cp = p & 63;
            float2 v = X2[p];
            __nv_bfloat16 h0 = __float2bfloat16(v.x);
            __nv_bfloat16 h1 = __float2bfloat16(v.y);
            float r0 = v.x - __bfloat162float(h0);
            float r1 = v.y - __bfloat162float(h1);
            int uidx = i * 64 + swz(i, cp >> 2) * 4 + (cp & 3);
            xh[uidx] = pkbf(__bfloat162float(h0), __bfloat162float(h1));
            xl[uidx] = pkbf(r0, r1);
        }
        for (int p = tid; p < (KPAD - L2DIM) * 64; p += NTHR) {
            int i = L2DIM + p / 64, c = p % 64;
            xh[i * 64 + c] = 0u;
            xl[i * 64 + c] = 0u;
        }
        uint4* sh = reinterpret_cast<uint4*>(smem + WFT_H);
        uint4* sl = reinterpret_cast<uint4*>(smem + WFT_L);
        const uint4* gh = reinterpret_cast<const uint4*>(g_WfTH);
        const uint4* gl = reinterpret_cast<const uint4*>(g_WfTL);
        for (int p = tid; p < IPAD * KBA * 2 / 16; p += NTHR) {
            sh[p] = gh[p];
            sl[p] = gl[p];
        }
    }

    // GEMM2 output accumulators (live across chunks)
    float d2[4][4];
#pragma unroll
    for (int a = 0; a < 4; a++)
#pragma unroll
        for (int b = 0; b < 4; b++) d2[a][b] = 0.0f;

    const int mtw = wrp >> 2;   // GEMM2: i-tile (rows mtw*16..+15)
    const int ntw = wrp & 3;    // GEMM2: c-group (cols ntw*32..+31)

    for (int ch = 0; ch < 3; ch++) {
        const int cbase = ch * CHUNK;
        __syncthreads();   // prev GEMM2 reads done before restage/epilogue
        // stage Wto chunk (raw copy; swizzle already applied with global rows)
        {
            uint4* sh = reinterpret_cast<uint4*>(smem + WTS_H);
            uint4* sl = reinterpret_cast<uint4*>(smem + WTS_L);
            const uint4* gh = reinterpret_cast<const uint4*>(g_WtoH) + cbase * 8;
            const uint4* gl = reinterpret_cast<const uint4*>(g_WtoL) + cbase * 8;
            for (int p = tid; p < CHUNK * 8; p += NTHR) {
                sh[p] = gh[p];
                sl[p] = gl[p];
            }
        }
        __syncthreads();

        // ---------------- GEMM1: D1[ba_local 112][c 128] ----------------
        if (wrp < 14) {
            const int mt = wrp >> 1;   // 0..6: rows mt*16..+15
            const int nt = wrp & 1;    // cols nt*64..+63
            float d1[8][4];
#pragma unroll
            for (int a = 0; a < 8; a++)
#pragma unroll
                for (int b = 0; b < 4; b++) d1[a][b] = 0.0f;

#pragma unroll
            for (int pass = 0; pass < 3; pass++) {
                const u32 abase = smem_u32 + (pass == 2 ? WTS_L : WTS_H);
                const u32 bbase = smem_u32 + (pass == 1 ? XS_L : XS_H);
#pragma unroll
                for (int ks = 0; ks < 4; ks++) {
                    int arow = mt * 16 + ((lane >> 3) & 1) * 8 + (lane & 7);
                    int achk = ks * 2 + (lane >> 4);
                    uint4 A = ldsm4(abase + arow * 128 + swz(cbase + arow, achk) * 16);
                    int krow = ks * 16 + ((lane >> 3) & 1) * 8 + (lane & 7);
#pragma unroll
                    for (int j = 0; j < 4; j++) {
                        int nchk = nt * 8 + j * 2 + (lane >> 4);
                        uint4 B = ldsm4t(bbase + krow * 256 + swz(krow, nchk) * 16);
                        mma16816(d1[2 * j],     A, B.x, B.y);
                        mma16816(d1[2 * j + 1], A, B.z, B.w);
                    }
                }
            }
            // epilogue: square, split hi/lo, store G2 (swizzled)
            u32* g2h = reinterpret_cast<u32*>(smem + G2_H);
            u32* g2l = reinterpret_cast<u32*>(smem + G2_L);
#pragma unroll
            for (int nn = 0; nn < 8; nn++) {
                int chk = nt * 8 + nn;
#pragma unroll
                for (int hr = 0; hr < 2; hr++) {
                    int row = mt * 16 + gg + hr * 8;
                    float s0 = d1[nn][hr * 2 + 0]; s0 *= s0;
                    float s1 = d1[nn][hr * 2 + 1]; s1 *= s1;
                    __nv_bfloat16 h0 = __float2bfloat16(s0);
                    __nv_bfloat16 h1 = __float2bfloat16(s1);
                    float r0 = s0 - __bfloat162float(h0);
                    float r1 = s1 - __bfloat162float(h1);
                    int uidx = row * 64 + swz(row, chk) * 4 + tc;
                    g2h[uidx] = pkbf(__bfloat162float(h0), __bfloat162float(h1));
                    g2l[uidx] = pkbf(r0, r1);
                }
            }
        }
        __syncthreads();

        // ---------------- GEMM2 partial: accumulate over this chunk's 112 ba ----------------
#pragma unroll
        for (int pass = 0; pass < 3; pass++) {
            const u32 abase = smem_u32 + (pass == 2 ? WFT_L : WFT_H);
            const u32 bbase = smem_u32 + (pass == 1 ? G2_L : G2_H);
#pragma unroll
            for (int ks = 0; ks < 7; ks++) {
                int arow = mtw * 16 + ((lane >> 3) & 1) * 8 + (lane & 7);
                int achk = cbase / 8 + ks * 2 + (lane >> 4);
                uint4 A = ldsm4(abase + arow * 768 + swz(arow, achk) * 16);
                int krow = ks * 16 + ((lane >> 3) & 1) * 8 + (lane & 7);
#pragma unroll
                for (int j = 0; j < 2; j++) {
                    int nchk = ntw * 4 + j * 2 + (lane >> 4);
                    uint4 B = ldsm4t(bbase + krow * 256 + swz(krow, nchk) * 16);
                    mma16816(d2[2 * j],     A, B.x, B.y);
                    mma16816(d2[2 * j + 1], A, B.z, B.w);
                }
            }
        }
    }

    // ---------------- writeout: D2[i][c] fp32 ----------------
    float2* O2 = reinterpret_cast<float2*>(Out + (size_t)n * L2DIM * CDIM);
#pragma unroll
    for (int nf = 0; nf < 4; nf++) {
        int c  = ntw * 32 + nf * 8 + tc * 2;
        int i0 = mtw * 16 + gg;
        if (i0 < L2DIM) O2[i0 * 64 + (c >> 1)] = make_float2(d2[nf][0], d2[nf][1]);
        int i1 = i0 + 8;
        if (i1 < L2DIM) O2[i1 * 64 + (c >> 1)] = make_float2(d2[nf][2], d2[nf][3]);
    }
}

// ---------------- launcher ----------------
extern "C" void kernel_launch(void* const* d_in, const int* in_sizes, int n_in,
                              void* d_out, int out_size) {
    const float* X   = (const float*)d_in[0];  // inputs  (N, 49, 128)
    const float* Wto = (const float*)d_in[1];  // W_to    (18, 18, 49)
    const float* Wf  = (const float*)d_in[2];  // W_from  (18, 18, 49)
    float* Out = (float*)d_out;                // (N, 49, 128)

    static bool attr_set = false;
    if (!attr_set) {
        cudaFuncSetAttribute(fused_kernel,
                             cudaFuncAttributeMaxDynamicSharedMemorySize,
                             SMEM_BYTES);
        attr_set = true;
    }

    int prep_total = MPAD * 64 + IPAD * KBA;   // 46080
    prep_kernel<<<(prep_total + 255) / 256, 256>>>(Wto, Wf);

    fused_kernel<<<NB, NTHR, SMEM_BYTES>>>(X, Out);
}

// round 14
// speedup vs baseline: 1.0027x; 1.0006x over previous
#include <cuda_runtime.h>
#include <cuda_bf16.h>
#include <cstdint>
#include <cstddef>

// Problem constants
#define NB    4096
#define L2DIM 49
#define CDIM  128
#define BAD   324
#define MPAD  336     // ba padded to 21 x 16 (GEMM1 M)
#define KPAD  64      // i padded (GEMM1 K)
#define IPAD  64      // i padded (GEMM2 M)
#define KBA   384     // ba padded (WfT row length, 48 x 16B chunks)
#define NTHR  512
#define CHUNK 112

typedef uint32_t u32;

// Bank swizzle: permute 16B chunks within a row; rows r and r+8 map differently
// in the low 3 bits so ldmatrix x4 half-tiles never collide.
__device__ __forceinline__ int swz(int row, int chunk) {
    return chunk ^ ((row + (row >> 3)) & 7);
}

// ---------------- device globals: pre-split, pre-swizzled weights ----------------
__device__ __nv_bfloat16 g_WtoH[MPAD * 64];    // [ba][i] rows 128B
__device__ __nv_bfloat16 g_WtoL[MPAD * 64];
__device__ __nv_bfloat16 g_WfTH[IPAD * KBA];   // [i][ba] rows 768B
__device__ __nv_bfloat16 g_WfTL[IPAD * KBA];

__global__ void prep_kernel(const float* __restrict__ Wto,
                            const float* __restrict__ Wf) {
    int idx = blockIdx.x * blockDim.x + threadIdx.x;
    if (idx < MPAD * 64) {
        int row = idx >> 6, col = idx & 63;
        float w = (row < BAD && col < L2DIM) ? Wto[row * L2DIM + col] : 0.0f;
        __nv_bfloat16 h = __float2bfloat16(w);
        __nv_bfloat16 l = __float2bfloat16(w - __bfloat162float(h));
        int pos = row * 64 + swz(row, col >> 3) * 8 + (col & 7);
        g_WtoH[pos] = h;
        g_WtoL[pos] = l;
    }
    int idx2 = idx - MPAD * 64;
    if (idx2 >= 0 && idx2 < IPAD * KBA) {
        int row = idx2 / KBA, col = idx2 - row * KBA;  // row = i, col = ba
        float w = (row < L2DIM && col < BAD) ? Wf[col * L2DIM + row] : 0.0f;
        __nv_bfloat16 h = __float2bfloat16(w);
        __nv_bfloat16 l = __float2bfloat16(w - __bfloat162float(h));
        int pos = row * KBA + swz(row, col >> 3) * 8 + (col & 7);
        g_WfTH[pos] = h;
        g_WfTL[pos] = l;
    }
}

// ---------------- mma / ldmatrix wrappers ----------------
__device__ __forceinline__ void mma16816(float* d, uint4 a, u32 b0, u32 b1) {
    asm volatile(
        "mma.sync.aligned.m16n8k16.row.col.f32.bf16.bf16.f32 "
        "{%0,%1,%2,%3}, {%4,%5,%6,%7}, {%8,%9}, {%0,%1,%2,%3};"
        : "+f"(d[0]), "+f"(d[1]), "+f"(d[2]), "+f"(d[3])
        : "r"(a.x), "r"(a.y), "r"(a.z), "r"(a.w), "r"(b0), "r"(b1));
}
__device__ __forceinline__ uint4 ldsm4(u32 addr) {
    uint4 r;
    asm volatile("ldmatrix.sync.aligned.m8n8.x4.shared.b16 {%0,%1,%2,%3}, [%4];"
                 : "=r"(r.x), "=r"(r.y), "=r"(r.z), "=r"(r.w) : "r"(addr));
    return r;
}
__device__ __forceinline__ uint4 ldsm4t(u32 addr) {
    uint4 r;
    asm volatile("ldmatrix.sync.aligned.m8n8.x4.trans.shared.b16 {%0,%1,%2,%3}, [%4];"
                 : "=r"(r.x), "=r"(r.y), "=r"(r.z), "=r"(r.w) : "r"(addr));
    return r;
}
__device__ __forceinline__ u32 pkbf(float a, float b) {
    __nv_bfloat162 t = __floats2bfloat162_rn(a, b);
    u32 r;
    memcpy(&r, &t, 4);
    return r;
}

// ---------------- SMEM layout (byte offsets), total 217088 ----------------
#define XS_H   0        // [64][128] bf16 rows 256B  (16384)
#define XS_L   16384
#define WTS_H  32768    // [112][64] bf16 rows 128B  (14336)
#define WTS_L  47104
#define G2_H   61440    // [112][128] bf16 rows 256B (28672)
#define G2_L   90112
#define WFT_H  118784   // [64][384] bf16 rows 768B  (49152)
#define WFT_L  167936
#define SMEM_BYTES 217088

__global__ void __launch_bounds__(NTHR, 1)
fused_kernel(const float* __restrict__ X, float* __restrict__ Out) {
    extern __shared__ __align__(16) char smem[];
    u32 smem_u32;
    asm("{ .reg .u64 t; cvta.to.shared.u64 t, %1; cvt.u32.u64 %0, t; }"
        : "=r"(smem_u32) : "l"(smem));

    const int n    = blockIdx.x;
    const int tid  = threadIdx.x;
    const int wrp  = tid >> 5;
    const int lane = tid & 31;
    const int gg   = lane >> 2;   // mma fragment row group
    const int tc   = lane & 3;    // mma fragment col/thread-in-group

    // ---------- stage X[n] split (hi/lo) + zero pad, and WfT copy ----------
    {
        const float2* X2 = reinterpret_cast<const float2*>(X + (size_t)n * L2DIM * CDIM);
        u32* xh = reinterpret_cast<u32*>(smem + XS_H);
        u32* xl = reinterpret_cast<u32*>(smem + XS_L);
        for (int p = tid; p < L2DIM * 64; p += NTHR) {
            int i = p >> 6, cp = p & 63;
            float2 v = X2[p];
            __nv_bfloat16 h0 = __float2bfloat16(v.x);
            __nv_bfloat16 h1 = __float2bfloat16(v.y);
            float r0 = v.x - __bfloat162float(h0);
            float r1 = v.y - __bfloat162float(h1);
            int uidx = i * 64 + swz(i, cp >> 2) * 4 + (cp & 3);
            xh[uidx] = pkbf(__bfloat162float(h0), __bfloat162float(h1));
            xl[uidx] = pkbf(r0, r1);
        }
        for (int p = tid; p < (KPAD - L2DIM) * 64; p += NTHR) {
            int i = L2DIM + p / 64, c = p % 64;
            xh[i * 64 + c] = 0u;
            xl[i * 64 + c] = 0u;
        }
        uint4* sh = reinterpret_cast<uint4*>(smem + WFT_H);
        uint4* sl = reinterpret_cast<uint4*>(smem + WFT_L);
        const uint4* gh = reinterpret_cast<const uint4*>(g_WfTH);
        const uint4* gl = reinterpret_cast<const uint4*>(g_WfTL);
        for (int p = tid; p < IPAD * KBA * 2 / 16; p += NTHR) {
            sh[p] = gh[p];
            sl[p] = gl[p];
        }
    }

    // GEMM2 output accumulators (live across chunks)
    float d2[4][4];
#pragma unroll
    for (int a = 0; a < 4; a++)
#pragma unroll
        for (int b = 0; b < 4; b++) d2[a][b] = 0.0f;

    const int mtw = wrp >> 2;   // GEMM2: i-tile (rows mtw*16..+15)
    const int ntw = wrp & 3;    // GEMM2: c-group (cols ntw*32..+31)

    for (int ch = 0; ch < 3; ch++) {
        const int cbase = ch * CHUNK;
        __syncthreads();   // prev GEMM2 reads done before restage/epilogue
        // stage Wto chunk (raw copy; swizzle already applied with global rows)
        {
            uint4* sh = reinterpret_cast<uint4*>(smem + WTS_H);
            uint4* sl = reinterpret_cast<uint4*>(smem + WTS_L);
            const uint4* gh = reinterpret_cast<const uint4*>(g_WtoH) + cbase * 8;
            const uint4* gl = reinterpret_cast<const uint4*>(g_WtoL) + cbase * 8;
            for (int p = tid; p < CHUNK * 8; p += NTHR) {
                sh[p] = gh[p];
                sl[p] = gl[p];
            }
        }
        __syncthreads();

        // ---------------- GEMM1: D1[ba_local 112][c 128] ----------------
        if (wrp < 14) {
            const int mt = wrp >> 1;   // 0..6: rows mt*16..+15
            const int nt = wrp & 1;    // cols nt*64..+63
            float d1[8][4];
#pragma unroll
            for (int a = 0; a < 8; a++)
#pragma unroll
                for (int b = 0; b < 4; b++) d1[a][b] = 0.0f;

#pragma unroll
            for (int pass = 0; pass < 3; pass++) {
                const u32 abase = smem_u32 + (pass == 2 ? WTS_L : WTS_H);
                const u32 bbase = smem_u32 + (pass == 1 ? XS_L : XS_H);
#pragma unroll
                for (int ks = 0; ks < 4; ks++) {
                    int arow = mt * 16 + ((lane >> 3) & 1) * 8 + (lane & 7);
                    int achk = ks * 2 + (lane >> 4);
                    uint4 A = ldsm4(abase + arow * 128 + swz(cbase + arow, achk) * 16);
                    int krow = ks * 16 + ((lane >> 3) & 1) * 8 + (lane & 7);
#pragma unroll
                    for (int j = 0; j < 4; j++) {
                        int nchk = nt * 8 + j * 2 + (lane >> 4);
                        uint4 B = ldsm4t(bbase + krow * 256 + swz(krow, nchk) * 16);
                        mma16816(d1[2 * j],     A, B.x, B.y);
                        mma16816(d1[2 * j + 1], A, B.z, B.w);
                    }
                }
            }
            // epilogue: square, split hi/lo, store G2 (swizzled)
            u32* g2h = reinterpret_cast<u32*>(smem + G2_H);
            u32* g2l = reinterpret_cast<u32*>(smem + G2_L);
#pragma unroll
            for (int nn = 0; nn < 8; nn++) {
                int chk = nt * 8 + nn;
#pragma unroll
                for (int hr = 0; hr < 2; hr++) {
                    int row = mt * 16 + gg + hr * 8;
                    float s0 = d1[nn][hr * 2 + 0]; s0 *= s0;
                    float s1 = d1[nn][hr * 2 + 1]; s1 *= s1;
                    __nv_bfloat16 h0 = __float2bfloat16(s0);
                    __nv_bfloat16 h1 = __float2bfloat16(s1);
                    float r0 = s0 - __bfloat162float(h0);
                    float r1 = s1 - __bfloat162float(h1);
                    int uidx = row * 64 + swz(row, chk) * 4 + tc;
                    g2h[uidx] = pkbf(__bfloat162float(h0), __bfloat162float(h1));
                    g2l[uidx] = pkbf(r0, r1);
                }
            }
        }
        __syncthreads();

        // ---------------- GEMM2 partial: accumulate over this chunk's 112 ba ----------------
#pragma unroll
        for (int pass = 0; pass < 3; pass++) {
            const u32 abase = smem_u32 + (pass == 2 ? WFT_L : WFT_H);
            const u32 bbase = smem_u32 + (pass == 1 ? G2_L : G2_H);
#pragma unroll
            for (int ks = 0; ks < 7; ks++) {
                int arow = mtw * 16 + ((lane >> 3) & 1) * 8 + (lane & 7);
                int achk = cbase / 8 + ks * 2 + (lane >> 4);
                uint4 A = ldsm4(abase + arow * 768 + swz(arow, achk) * 16);
                int krow = ks * 16 + ((lane >> 3) & 1) * 8 + (lane & 7);
#pragma unroll
                for (int j = 0; j < 2; j++) {
                    int nchk = ntw * 4 + j * 2 + (lane >> 4);
                    uint4 B = ldsm4t(bbase + krow * 256 + swz(krow, nchk) * 16);
                    mma16816(d2[2 * j],     A, B.x, B.y);
                    mma16816(d2[2 * j + 1], A, B.z, B.w);
                }
            }
        }
    }

    // ---------------- writeout: D2[i][c] fp32 ----------------
    float2* O2 = reinterpret_cast<float2*>(Out + (size_t)n * L2DIM * CDIM);
#pragma unroll
    for (int nf = 0; nf < 4; nf++) {
        int c  = ntw * 32 + nf * 8 + tc * 2;
        int i0 = mtw * 16 + gg;
        if (i0 < L2DIM) O2[i0 * 64 + (c >> 1)] = make_float2(d2[nf][0], d2[nf][1]);
        int i1 = i0 + 8;
        if (i1 < L2DIM) O2[i1 * 64 + (c >> 1)] = make_float2(d2[nf][2], d2[nf][3]);
    }
}

// ---------------- launcher ----------------
extern "C" void kernel_launch(void* const* d_in, const int* in_sizes, int n_in,
                              void* d_out, int out_size) {
    const float* X   = (const float*)d_in[0];  // inputs  (N, 49, 128)
    const float* Wto = (const float*)d_in[1];  // W_to    (18, 18, 49)
    const float* Wf  = (const float*)d_in[2];  // W_from  (18, 18, 49)
    float* Out = (float*)d_out;                // (N, 49, 128)

    static bool attr_set = false;
    if (!attr_set) {
        cudaFuncSetAttribute(fused_kernel,
                             cudaFuncAttributeMaxDynamicSharedMemorySize,
                             SMEM_BYTES);
        attr_set = true;
    }

    int prep_total = MPAD * 64 + IPAD * KBA;   // 46080
    prep_kernel<<<(prep_total + 255) / 256, 256>>>(Wto, Wf);

    fused_kernel<<<NB, NTHR, SMEM_BYTES>>>(X, Out);
}